// round 5
// baseline (speedup 1.0000x reference)
#include <cuda_runtime.h>
#include <cstdint>

#define N_NODES 8192
#define N_COMM 16
#define DIMS 64
#define S2_BLOCKS 1024

// Scratch (no device allocation allowed) — fully rewritten every launch.
__device__ float g_pi[N_NODES * N_COMM];
__device__ float g_partI[S2_BLOCKS];
__device__ float g_partR[S2_BLOCKS];

// ---- packed f32x2 helpers (sm_103a; ptxas never emits these from C++) ----
__device__ __forceinline__ unsigned long long fma2(unsigned long long a,
                                                   unsigned long long b,
                                                   unsigned long long c) {
    unsigned long long d;
    asm("fma.rn.f32x2 %0, %1, %2, %3;" : "=l"(d) : "l"(a), "l"(b), "l"(c));
    return d;
}
__device__ __forceinline__ unsigned long long pack2(float x, float y) {
    unsigned long long r;
    asm("mov.b64 %0, {%1, %2};" : "=l"(r) : "f"(x), "f"(y));
    return r;
}
__device__ __forceinline__ float2 unpack2(unsigned long long v) {
    float2 f;
    asm("mov.b64 {%0, %1}, %2;" : "=f"(f.x), "=f"(f.y) : "l"(v));
    return f;
}

// ============================================================================
// Stage 1: distances over 3 manifolds -> dist_norm -> softmax -> g_pi
// 2 nodes per warp (half-warp of 16 lanes = 16 communities per node).
// ============================================================================
__global__ __launch_bounds__(256) void stage1(const float* __restrict__ ne,
                                              const float* __restrict__ comm) {
    __shared__ float sC[DIMS * N_COMM];  // transposed: sC[d*16 + k]
    int tid = threadIdx.x;
    for (int e = tid; e < DIMS * N_COMM; e += 256) {
        int d = e >> 4, k = e & 15;
        sC[e] = comm[k * DIMS + d];
    }
    __syncthreads();

    int warp = tid >> 5, lane = tid & 31;
    int half = lane >> 4, k = lane & 15;
    int node = blockIdx.x * 16 + warp * 2 + half;

    const float* x0 = ne + (size_t)node * DIMS;
    const float* x1 = x0 + (size_t)N_NODES * DIMS;
    const float* x2 = x1 + (size_t)N_NODES * DIMS;

    float accE = 0.f, acc1 = 0.f, acc2 = 0.f;
    float t0 = __ldg(x1) * sC[k];  // x1[0]*c[0] for Lorentz inner product
#pragma unroll 8
    for (int d = 0; d < DIMS; ++d) {
        float c = sC[d * 16 + k];
        float a0 = __ldg(x0 + d);
        float a1 = __ldg(x1 + d);
        float a2 = __ldg(x2 + d);
        float df = a0 - c;
        accE = fmaf(df, df, accE);   // Euclidean ||x-c||^2
        acc1 = fmaf(a1, c, acc1);    // <x,c> for Lorentz
        acc2 = fmaf(a2, c, acc2);    // <x,c> for Sphere
    }
    // Lorentz (k=-1, kk=1): lip = <x,c> - 2*x0*c0 ; d = acosh(max(-lip, 1+eps))
    float lip = acc1 - 2.f * t0;
    float arg = fmaxf(-lip, 1.0000001f);          // f32 round of 1+1e-7 (matches jax)
    float dl = acoshf(arg);
    // Sphere: d = acos(clip(<x,c>, -1+eps, 1-eps))
    float cs = fminf(fmaxf(acc2, -0.9999999f), 0.9999999f);
    float ds = acosf(cs);
    // dist_norm over manifolds
    float dn = sqrtf(accE + dl * dl + ds * ds);

    // softmax over the 16 lanes of this half-warp
    float m = dn;
#pragma unroll
    for (int o = 8; o; o >>= 1) m = fmaxf(m, __shfl_xor_sync(0xffffffffu, m, o, 16));
    float e = expf(dn - m);
    float s = e;
#pragma unroll
    for (int o = 8; o; o >>= 1) s += __shfl_xor_sync(0xffffffffu, s, o, 16);

    g_pi[node * N_COMM + k] = e / s;
}

// ============================================================================
// Stage 2: single streaming pass over ricci.
//   partI = sum_ij R_ij * (pi_i . pi_j)        (intra numerator)
//   partR = sum_ij R_ij                        (inter numerator; s == 1)
// Tiling: 1024 blocks; tile = 128 rows x 512 cols. Warp owns 64 cols; lane
// owns 2 cols with pi_j register-resident as 8 f32x2 each. pi_i broadcast
// from shared (8 LDS.64 amortized over 2 elements).
// ============================================================================
__global__ __launch_bounds__(256) void stage2(const float* __restrict__ R) {
    __shared__ __align__(16) float sPi[128 * N_COMM];
    __shared__ float redI[8], redR[8];

    int tid = threadIdx.x;
    int tile = blockIdx.x;
    int it = tile >> 4;   // 0..63  (row tile)
    int jt = tile & 15;   // 0..15  (col tile)
    int i0 = it * 128;

    // stage pi rows [i0, i0+128) into shared
    {
        const float4* src = reinterpret_cast<const float4*>(g_pi + (size_t)i0 * N_COMM);
        float4* dst = reinterpret_cast<float4*>(sPi);
        for (int e = tid; e < 128 * N_COMM / 4; e += 256) dst[e] = src[e];
    }
    __syncthreads();

    int warp = tid >> 5, lane = tid & 31;
    int jb = jt * 512 + warp * 64 + lane * 2;

    // register-resident pi for this lane's two j columns (8 f32x2 each)
    const unsigned long long* gp = reinterpret_cast<const unsigned long long*>(g_pi);
    unsigned long long pj0[8], pj1[8];
#pragma unroll
    for (int m = 0; m < 8; ++m) {
        pj0[m] = gp[(size_t)jb * 8 + m];
        pj1[m] = gp[(size_t)(jb + 1) * 8 + m];
    }

    const unsigned long long* sq = reinterpret_cast<const unsigned long long*>(sPi);
    const float2* Rp = reinterpret_cast<const float2*>(R + (size_t)i0 * N_NODES + jb);

    unsigned long long acc = 0ull;  // two f32 accumulators (intra)
    float accR = 0.f;               // plain sum of R (inter)

#pragma unroll 4
    for (int i = 0; i < 128; ++i) {
        float2 r = __ldg(Rp + (size_t)i * (N_NODES / 2));
        const unsigned long long* q = sq + i * 8;
        unsigned long long t0 = 0ull, t1 = 0ull;   // 2-wide partial dots
#pragma unroll
        for (int m = 0; m < 8; ++m) {
            unsigned long long qm = q[m];          // pi_i pair (broadcast LDS.64)
            t0 = fma2(qm, pj0[m], t0);
            t1 = fma2(qm, pj1[m], t1);
        }
        acc = fma2(pack2(r.x, r.x), t0, acc);
        acc = fma2(pack2(r.y, r.y), t1, acc);
        accR += r.x + r.y;
    }

    float2 a = unpack2(acc);
    float aI = a.x + a.y;
#pragma unroll
    for (int o = 16; o; o >>= 1) {
        aI   += __shfl_xor_sync(0xffffffffu, aI, o);
        accR += __shfl_xor_sync(0xffffffffu, accR, o);
    }
    if (lane == 0) { redI[warp] = aI; redR[warp] = accR; }
    __syncthreads();
    if (tid == 0) {
        float sI = 0.f, sR = 0.f;
#pragma unroll
        for (int w = 0; w < 8; ++w) { sI += redI[w]; sR += redR[w]; }
        g_partI[blockIdx.x] = sI;
        g_partR[blockIdx.x] = sR;
    }
}

// ============================================================================
// Stage 3: deterministic fixed-order reduction of block partials + combine.
//   out = alpha * intra_sum/(K*N) - R_sum/(K*K*N)
// ============================================================================
__global__ __launch_bounds__(256) void finalize(const float* __restrict__ alpha,
                                                float* __restrict__ out) {
    __shared__ float sI[256], sR[256];
    int t = threadIdx.x;
    float aI = 0.f, aR = 0.f;
    for (int b = t; b < S2_BLOCKS; b += 256) { aI += g_partI[b]; aR += g_partR[b]; }
    sI[t] = aI; sR[t] = aR;
    __syncthreads();
    for (int s = 128; s; s >>= 1) {
        if (t < s) { sI[t] += sI[t + s]; sR[t] += sR[t + s]; }
        __syncthreads();
    }
    if (t == 0) {
        // K*N = 131072 ; K*K*N = 2097152
        out[0] = alpha[0] * (sI[0] / 131072.0f) - sR[0] / 2097152.0f;
    }
}

extern "C" void kernel_launch(void* const* d_in, const int* in_sizes, int n_in,
                              void* d_out, int out_size) {
    const float* ne    = (const float*)d_in[0];  // (3, 8192, 64) f32
    const float* comm  = (const float*)d_in[1];  // (16, 64) f32
    const float* ricci = (const float*)d_in[2];  // (8192, 8192) f32
    const float* alpha = (const float*)d_in[3];  // scalar f32
    float* out = (float*)d_out;                  // 1 element f32

    stage1<<<N_NODES / 16, 256>>>(ne, comm);
    stage2<<<S2_BLOCKS, 256>>>(ricci);
    finalize<<<1, 256>>>(alpha, out);
}